// round 8
// baseline (speedup 1.0000x reference)
#include <cuda_runtime.h>

#define B_DIM   256
#define OUT_DIM 256
#define IN_DIM  256
#define G_DIM   8
#define LOG2E   1.44269504088896340736f
#define LN2     0.69314718055994530942f

#define OT    16
#define BT    32
#define IC    32
#define Z     2
#define IHALF (IN_DIM / Z)      // 128
#define NCH   (IHALF / IC)      // 4
#define CELLF 20                // floats per (ii,o) cell: A0,B0..A8,B8,s,base*ln2
#define IISTR 322               // floats per ii slice: 16*20 + 2 pad (322 mod 32 = 2)
#define XNSTR 36                // 36*4 = 144 bytes: keeps float4 stores 16B-aligned

// Precomputed scratch (device globals; no allocation).
__device__ float          g_xn[IN_DIM * B_DIM];            // [i][b]: tanh(x)*log2e
__device__ unsigned short g_kp[(B_DIM / 2) * IN_DIM];      // [bpair][i]: (k0*8)|(k1*8)<<8
__device__ float2         g_AB2[10][OUT_DIM * IN_DIM];     // [k][o*IN+i]: k<9 {A_k,B_k}; k=9 {s, base*ln2}

__device__ __forceinline__ float rcp_f(float a) {
    float r; asm("rcp.approx.f32 %0, %1;" : "=f"(r) : "f"(a)); return r;
}
__device__ __forceinline__ float ex2_f(float a) {
    float r; asm("ex2.approx.f32 %0, %1;" : "=f"(r) : "f"(a)); return r;
}
__device__ __forceinline__ float tanh_fast(float x) {
    float e = __expf(2.0f * x);                 // saturates correctly at +/-inf
    return 1.0f - __fdividef(2.0f, e + 1.0f);
}

// ---------------------------------------------------------------------------
// Prep kernel: blocks [0,128) do xn/k; blocks [128,384) do A/B tables.
// ---------------------------------------------------------------------------
__global__ __launch_bounds__(256)
void k_prep(const float* __restrict__ x,
            const float* __restrict__ w,
            const float* __restrict__ scaler,
            const float* __restrict__ base_,
            const float* __restrict__ grid)
{
    const float g0    = __ldg(grid);
    const float g7    = __ldg(grid + (G_DIM - 1));
    const float step  = (g7 - g0) * (1.0f / (float)(G_DIM - 1));
    const float inv_h = (float)(G_DIM - 1) / (g7 - g0);

    if (blockIdx.x < 128) {
        // ---- xn / k ----
        int u    = blockIdx.x * 256 + threadIdx.x;   // 0..32767
        int pair = u >> 8;                           // 0..127
        int i    = u & 255;
        int b    = pair * 2;
        float xn0 = tanh_fast(x[b * IN_DIM + i]);
        float xn1 = tanh_fast(x[(b + 1) * IN_DIM + i]);
        int k0 = 1 + __float2int_rd((xn0 - g0) * inv_h);
        int k1 = 1 + __float2int_rd((xn1 - g0) * inv_h);
        k0 = max(0, min(8, k0));
        k1 = max(0, min(8, k1));
        *(float2*)&g_xn[i * B_DIM + b] = make_float2(xn0 * LOG2E, xn1 * LOG2E);
        g_kp[pair * IN_DIM + i] = (unsigned short)((k0 * 8) | ((k1 * 8) << 8));
    } else {
        // ---- A/B prefix tables ----
        int v = (blockIdx.x - 128) * 256 + threadIdx.x;  // o*IN + i, 0..65535
        float s = scaler[v];
        float4 w0 = *(const float4*)(w + v * G_DIM);
        float4 w1 = *(const float4*)(w + v * G_DIM + 4);
        float wv[G_DIM] = {w0.x, w0.y, w0.z, w0.w, w1.x, w1.y, w1.z, w1.w};
        float Ep = __expf(s * step);
        float ep = __expf(s * g0);
        float Eq = rcp_f(Ep);
        float eq = rcp_f(ep);
        float p[G_DIM], q[G_DIM];
#pragma unroll
        for (int g = 0; g < G_DIM; g++) {
            p[g] = wv[g] * ep;  ep *= Ep;   // w_g * e^{ s*grid_g}
            q[g] = wv[g] * eq;  eq *= Eq;   // w_g * e^{-s*grid_g}
        }
        float A[9], Bv[9];
        A[0] = 0.f;
#pragma unroll
        for (int k = 0; k < 8; k++) A[k + 1] = A[k] + p[k];
        Bv[8] = 0.f;
#pragma unroll
        for (int k = 7; k >= 0; k--) Bv[k] = Bv[k + 1] + q[k];
#pragma unroll
        for (int k = 0; k < 9; k++) g_AB2[k][v] = make_float2(A[k], Bv[k]);
        g_AB2[9][v] = make_float2(s, base_[v] * LN2);
    }
}

// ---------------------------------------------------------------------------
// Main kernel: CTA = 32b x 16o x IHALF i; thread = (2b x 2o); stage + consume.
//   contribution = A_k*2^{-t} + B_k*2^{t} + base'*xn',  t = s*xn'
// ---------------------------------------------------------------------------
__global__ __launch_bounds__(128, 2)
void k_main(float* __restrict__ out)
{
    __shared__ float          sh_xn[IC][XNSTR];
    __shared__ unsigned short sh_kp[BT / 2][IC];
    __shared__ float          sh_ab[IC * IISTR];

    const int tid   = threadIdx.x;
    const int opair = tid & 7;       // o = o0 + 2*opair (+0/1)
    const int bpair = tid >> 3;      // 0..15, b = b0 + 2*bpair (+0/1)
    const int o0    = blockIdx.x * OT;
    const int b0    = blockIdx.y * BT;
    const int i00   = blockIdx.z * IHALF;

    float acc00 = 0.f, acc01 = 0.f, acc10 = 0.f, acc11 = 0.f;

#pragma unroll 1
    for (int c = 0; c < NCH; c++) {
        const int i0 = i00 + c * IC;

        // ---- stage xn: 32 ii x 32 b floats (4KB) ----
        {
            int ii = tid >> 3, b4 = (tid & 7) * 4;
#pragma unroll
            for (int j = 0; j < 2; j++) {
                float4 v = *(const float4*)&g_xn[(i0 + ii + j * 16) * B_DIM + b0 + b4];
                *(float4*)&sh_xn[ii + j * 16][b4] = v;
            }
        }
        // ---- stage k-pack: 16 pairs x 32 ii u16 (1KB) ----
        {
            int pr = tid >> 3, i4 = (tid & 7) * 4;
            *(uint2*)&sh_kp[pr][i4] =
                *(const uint2*)&g_kp[(b0 / 2 + pr) * IN_DIM + i0 + i4];
        }
        // ---- stage AB cells: 10 k x 16 o x 32 ii float2 (40KB) ----
#pragma unroll
        for (int un = 0; un < 20; un++) {
            int e   = tid + un * 128;      // 0..2559
            int row = e >> 4;              // 0..159
            int k   = row >> 4;            // 0..9
            int o   = row & 15;
            int iip = (e & 15) * 2;        // ii pair
            float4 v = *(const float4*)&g_AB2[k][(o0 + o) * IN_DIM + i0 + iip];
            float* cell = &sh_ab[iip * IISTR + o * CELLF + 2 * k];
            *(float2*)cell           = make_float2(v.x, v.y);
            *(float2*)(cell + IISTR) = make_float2(v.z, v.w);
        }
        __syncthreads();

        // ---- consume: 4 triples per ii per thread ----
        const float* rbase = sh_ab + opair * (2 * CELLF);     // o = 2*opair
#pragma unroll
        for (int ii = 0; ii < IC; ii++) {
            float2 xn2 = *(const float2*)&sh_xn[ii][2 * bpair];
            unsigned int kk = sh_kp[bpair][ii];
            const char* rp  = (const char*)(rbase + ii * IISTR);
            float2 sb0 = *(const float2*)(rp + 72);           // {s, base*ln2} for o
            float2 sb1 = *(const float2*)(rp + 80 + 72);      // ... for o+1
            const char* p0 = rp + (kk & 0xFFu);               // k0*8
            const char* p1 = rp + (kk >> 8);                  // k1*8
            float2 a00 = *(const float2*)(p0);
            float2 a01 = *(const float2*)(p0 + 80);
            float2 a10 = *(const float2*)(p1);
            float2 a11 = *(const float2*)(p1 + 80);
            float t00 = sb0.x * xn2.x, t01 = sb1.x * xn2.x;
            float t10 = sb0.x * xn2.y, t11 = sb1.x * xn2.y;
            float u00 = ex2_f(t00), r00 = rcp_f(u00);
            float u01 = ex2_f(t01), r01 = rcp_f(u01);
            float u10 = ex2_f(t10), r10 = rcp_f(u10);
            float u11 = ex2_f(t11), r11 = rcp_f(u11);
            acc00 = fmaf(a00.x, r00, fmaf(a00.y, u00, fmaf(sb0.y, xn2.x, acc00)));
            acc01 = fmaf(a01.x, r01, fmaf(a01.y, u01, fmaf(sb1.y, xn2.x, acc01)));
            acc10 = fmaf(a10.x, r10, fmaf(a10.y, u10, fmaf(sb0.y, xn2.y, acc10)));
            acc11 = fmaf(a11.x, r11, fmaf(a11.y, u11, fmaf(sb1.y, xn2.y, acc11)));
        }
        __syncthreads();
    }

    // Z=2: exactly two commutative atomic adds per output from 0 -> deterministic
    int b = b0 + 2 * bpair, o = o0 + 2 * opair;
    atomicAdd(&out[b * OUT_DIM + o],           acc00);
    atomicAdd(&out[b * OUT_DIM + o + 1],       acc01);
    atomicAdd(&out[(b + 1) * OUT_DIM + o],     acc10);
    atomicAdd(&out[(b + 1) * OUT_DIM + o + 1], acc11);
}

// ---------------------------------------------------------------------------
extern "C" void kernel_launch(void* const* d_in, const int* in_sizes, int n_in,
                              void* d_out, int out_size)
{
    const float* x      = (const float*)d_in[0];
    const float* w      = (const float*)d_in[1];
    const float* scaler = (const float*)d_in[2];
    const float* base   = (const float*)d_in[3];
    const float* grid   = (const float*)d_in[4];
    float* out = (float*)d_out;

    cudaMemsetAsync(out, 0, (size_t)out_size * sizeof(float));
    k_prep<<<384, 256>>>(x, w, scaler, base, grid);
    dim3 g(OUT_DIM / OT, B_DIM / BT, Z);    // 16 x 8 x 2 = 256 CTAs
    k_main<<<g, 128>>>(out);
}

// round 10
// speedup vs baseline: 1.1709x; 1.1709x over previous
#include <cuda_runtime.h>

#define B_DIM   256
#define OUT_DIM 256
#define IN_DIM  256
#define G_DIM   8
#define LOG2E   1.44269504088896340736f
#define LN2     0.69314718055994530942f

#define OT    8
#define BT    32
#define IC    32
#define Z     2
#define IHALF (IN_DIM / Z)      // 128
#define NCH   (IHALF / IC)      // 4
#define CELLF 20                // floats per (ii,o) cell: A0,B0..A8,B8,s,base*ln2
#define IISTR 162               // floats per ii slice: 8*20 + 2 pad (mod 32 = 2)
#define XNSTR 36                // xn row stride (floats); 144B keeps float4 stores aligned

// Precomputed scratch (device globals; no allocation).
__device__ float          g_xn[IN_DIM * B_DIM];            // [i][b]: tanh(x)*log2e
__device__ unsigned short g_kp[(B_DIM / 2) * IN_DIM];      // [bpair][i]: (k0*8)|(k1*8)<<8
__device__ float2         g_AB2[10][OUT_DIM * IN_DIM];     // [k][o*IN+i]: k<9 {A_k,B_k}; k=9 {s, base*ln2}

__device__ __forceinline__ float rcp_f(float a) {
    float r; asm("rcp.approx.f32 %0, %1;" : "=f"(r) : "f"(a)); return r;
}
__device__ __forceinline__ float ex2_f(float a) {
    float r; asm("ex2.approx.f32 %0, %1;" : "=f"(r) : "f"(a)); return r;
}
__device__ __forceinline__ float tanh_fast(float x) {
    float e = __expf(2.0f * x);                 // saturates correctly at +/-inf
    return 1.0f - __fdividef(2.0f, e + 1.0f);
}

// ---------------------------------------------------------------------------
// Prep kernel: blocks [0,128) do xn/k; blocks [128,384) do A/B tables.
// ---------------------------------------------------------------------------
__global__ __launch_bounds__(256)
void k_prep(const float* __restrict__ x,
            const float* __restrict__ w,
            const float* __restrict__ scaler,
            const float* __restrict__ base_,
            const float* __restrict__ grid)
{
    const float g0    = __ldg(grid);
    const float g7    = __ldg(grid + (G_DIM - 1));
    const float step  = (g7 - g0) * (1.0f / (float)(G_DIM - 1));
    const float inv_h = (float)(G_DIM - 1) / (g7 - g0);

    if (blockIdx.x < 128) {
        // ---- xn / k ----
        int u    = blockIdx.x * 256 + threadIdx.x;   // 0..32767
        int pair = u >> 8;                           // 0..127
        int i    = u & 255;
        int b    = pair * 2;
        float xn0 = tanh_fast(x[b * IN_DIM + i]);
        float xn1 = tanh_fast(x[(b + 1) * IN_DIM + i]);
        int k0 = 1 + __float2int_rd((xn0 - g0) * inv_h);
        int k1 = 1 + __float2int_rd((xn1 - g0) * inv_h);
        k0 = max(0, min(8, k0));
        k1 = max(0, min(8, k1));
        *(float2*)&g_xn[i * B_DIM + b] = make_float2(xn0 * LOG2E, xn1 * LOG2E);
        g_kp[pair * IN_DIM + i] = (unsigned short)((k0 * 8) | ((k1 * 8) << 8));
    } else {
        // ---- A/B prefix tables ----
        int v = (blockIdx.x - 128) * 256 + threadIdx.x;  // o*IN + i
        float s = scaler[v];
        float4 w0 = *(const float4*)(w + v * G_DIM);
        float4 w1 = *(const float4*)(w + v * G_DIM + 4);
        float wv[G_DIM] = {w0.x, w0.y, w0.z, w0.w, w1.x, w1.y, w1.z, w1.w};
        float Ep = __expf(s * step);
        float ep = __expf(s * g0);
        float Eq = rcp_f(Ep);
        float eq = rcp_f(ep);
        float p[G_DIM], q[G_DIM];
#pragma unroll
        for (int g = 0; g < G_DIM; g++) {
            p[g] = wv[g] * ep;  ep *= Ep;   // w_g * e^{ s*grid_g}
            q[g] = wv[g] * eq;  eq *= Eq;   // w_g * e^{-s*grid_g}
        }
        float A[9], Bv[9];
        A[0] = 0.f;
#pragma unroll
        for (int k = 0; k < 8; k++) A[k + 1] = A[k] + p[k];
        Bv[8] = 0.f;
#pragma unroll
        for (int k = 7; k >= 0; k--) Bv[k] = Bv[k + 1] + q[k];
#pragma unroll
        for (int k = 0; k < 9; k++) g_AB2[k][v] = make_float2(A[k], Bv[k]);
        g_AB2[9][v] = make_float2(s, base_[v] * LN2);
    }
}

// ---------------------------------------------------------------------------
// Main kernel: CTA = 32b x 8o x IHALF i; thread = (b-pair, o); stage + consume.
//   contribution = A_k*2^{-t} + B_k*2^{t} + base'*xn',  t = s*xn'
// ---------------------------------------------------------------------------
__global__ __launch_bounds__(128, 6)
void k_main(float* __restrict__ out)
{
    __shared__ float          sh_xn[IC][XNSTR];     // 4.6KB
    __shared__ unsigned short sh_kp[BT / 2][IC];    // 1KB
    __shared__ float          sh_ab[IC * IISTR];    // 20.7KB

    const int tid     = threadIdx.x;
    const int o_local = tid & 7;         // o = o0 + o_local
    const int bpair   = tid >> 3;        // 0..15 -> b = b0 + 2*bpair (+0/1)
    const int o0      = blockIdx.x * OT;
    const int b0      = blockIdx.y * BT;
    const int i00     = blockIdx.z * IHALF;

    float acc0 = 0.f, acc1 = 0.f;

#pragma unroll 1
    for (int c = 0; c < NCH; c++) {
        const int i0 = i00 + c * IC;

        // ---- stage xn: 32 ii x 32 b floats (4KB) ----
        {
            int ii = tid >> 3, b4 = (tid & 7) * 4;
#pragma unroll
            for (int j = 0; j < 2; j++) {
                float4 v = *(const float4*)&g_xn[(i0 + ii + j * 16) * B_DIM + b0 + b4];
                *(float4*)&sh_xn[ii + j * 16][b4] = v;
            }
        }
        // ---- stage k-pack: 16 pairs x 32 ii u16 (1KB) ----
        {
            int pr = tid >> 3, i4 = (tid & 7) * 4;
            *(uint2*)&sh_kp[pr][i4] =
                *(const uint2*)&g_kp[(b0 / 2 + pr) * IN_DIM + i0 + i4];
        }
        // ---- stage AB cells: 10 k x 8 o x 32 ii float2 (20KB), float4 = 2 ii ----
#pragma unroll
        for (int un = 0; un < 10; un++) {
            int e   = tid + un * 128;      // 0..1279
            int row = e >> 4;              // 0..79
            int k   = row >> 3;            // 0..9
            int o   = row & 7;
            int iip = (e & 15) * 2;        // ii pair
            float4 v = *(const float4*)&g_AB2[k][(o0 + o) * IN_DIM + i0 + iip];
            float* cell = &sh_ab[iip * IISTR + o * CELLF + 2 * k];
            *(float2*)cell           = make_float2(v.x, v.y);
            *(float2*)(cell + IISTR) = make_float2(v.z, v.w);
        }
        __syncthreads();

        // ---- consume: 2 triples per ii per thread ----
        const float* rbase = sh_ab + o_local * CELLF;
        const unsigned short* kprow = &sh_kp[bpair][0];
#pragma unroll
        for (int ii = 0; ii < IC; ii++) {
            float2 xn2 = *(const float2*)&sh_xn[ii][2 * bpair];
            unsigned int kk = kprow[ii];
            const char* rp = (const char*)(rbase + ii * IISTR);
            float2 sb = *(const float2*)(rp + 72);            // {s, base*ln2}
            float2 a0 = *(const float2*)(rp + (kk & 0xFFu));  // {A,B} for b
            float2 a1 = *(const float2*)(rp + (kk >> 8));     // {A,B} for b+1
            float t0 = sb.x * xn2.x;
            float t1 = sb.x * xn2.y;
            float u0 = ex2_f(t0), r0 = rcp_f(u0);
            float u1 = ex2_f(t1), r1 = rcp_f(u1);
            acc0 = fmaf(a0.x, r0, fmaf(a0.y, u0, fmaf(sb.y, xn2.x, acc0)));
            acc1 = fmaf(a1.x, r1, fmaf(a1.y, u1, fmaf(sb.y, xn2.y, acc1)));
        }
        __syncthreads();
    }

    // Z=2: exactly two commutative atomic adds per output from 0 -> deterministic
    int b = b0 + 2 * bpair, o = o0 + o_local;
    atomicAdd(&out[b * OUT_DIM + o],       acc0);
    atomicAdd(&out[(b + 1) * OUT_DIM + o], acc1);
}

// ---------------------------------------------------------------------------
extern "C" void kernel_launch(void* const* d_in, const int* in_sizes, int n_in,
                              void* d_out, int out_size)
{
    const float* x      = (const float*)d_in[0];
    const float* w      = (const float*)d_in[1];
    const float* scaler = (const float*)d_in[2];
    const float* base   = (const float*)d_in[3];
    const float* grid   = (const float*)d_in[4];
    float* out = (float*)d_out;

    cudaMemsetAsync(out, 0, (size_t)out_size * sizeof(float));
    k_prep<<<384, 256>>>(x, w, scaler, base, grid);
    dim3 g(OUT_DIM / OT, B_DIM / BT, Z);    // 32 x 8 x 2 = 512 CTAs
    k_main<<<g, 128>>>(out);
}

// round 11
// speedup vs baseline: 1.2047x; 1.0289x over previous
#include <cuda_runtime.h>

#define B_DIM   256
#define OUT_DIM 256
#define IN_DIM  256
#define G_DIM   8
#define LOG2E   1.44269504088896340736f
#define LN2     0.69314718055994530942f

#define OT    8
#define BT    32
#define IC    32
#define Z     4
#define IPART (IN_DIM / Z)      // 64
#define NCH   (IPART / IC)      // 2
#define CELLF 20                // floats per (ii,o) cell: A0,B0..A8,B8,s,base*ln2
#define IISTR 162               // floats per ii slice: 8*20 + 2 pad (mod 32 = 2)
#define XNSTR 36                // xn row stride (floats); keeps float4 stores aligned

// Precomputed scratch (device globals; no allocation).
__device__ float          g_xn[IN_DIM * B_DIM];            // [i][b]: tanh(x)*log2e
__device__ unsigned short g_kp[(B_DIM / 2) * IN_DIM];      // [bpair][i]: (k0*8)|(k1*8)<<8
__device__ float2         g_AB2[10][OUT_DIM * IN_DIM];     // [k][o*IN+i]: k<9 {A_k,B_k}; k=9 {s, base*ln2}

__device__ __forceinline__ float rcp_f(float a) {
    float r; asm("rcp.approx.f32 %0, %1;" : "=f"(r) : "f"(a)); return r;
}
__device__ __forceinline__ float ex2_f(float a) {
    float r; asm("ex2.approx.f32 %0, %1;" : "=f"(r) : "f"(a)); return r;
}
__device__ __forceinline__ float tanh_fast(float x) {
    float e = __expf(2.0f * x);                 // saturates correctly at +/-inf
    return 1.0f - __fdividef(2.0f, e + 1.0f);
}

// ---------------------------------------------------------------------------
// Prep kernel: blocks [0,128) do xn/k; blocks [128,384) do A/B tables.
// ---------------------------------------------------------------------------
__global__ __launch_bounds__(256)
void k_prep(const float* __restrict__ x,
            const float* __restrict__ w,
            const float* __restrict__ scaler,
            const float* __restrict__ base_,
            const float* __restrict__ grid)
{
    const float g0    = __ldg(grid);
    const float g7    = __ldg(grid + (G_DIM - 1));
    const float step  = (g7 - g0) * (1.0f / (float)(G_DIM - 1));
    const float inv_h = (float)(G_DIM - 1) / (g7 - g0);

    if (blockIdx.x < 128) {
        // ---- xn / k ----
        int u    = blockIdx.x * 256 + threadIdx.x;   // 0..32767
        int pair = u >> 8;                           // 0..127
        int i    = u & 255;
        int b    = pair * 2;
        float xn0 = tanh_fast(x[b * IN_DIM + i]);
        float xn1 = tanh_fast(x[(b + 1) * IN_DIM + i]);
        int k0 = 1 + __float2int_rd((xn0 - g0) * inv_h);
        int k1 = 1 + __float2int_rd((xn1 - g0) * inv_h);
        k0 = max(0, min(8, k0));
        k1 = max(0, min(8, k1));
        *(float2*)&g_xn[i * B_DIM + b] = make_float2(xn0 * LOG2E, xn1 * LOG2E);
        g_kp[pair * IN_DIM + i] = (unsigned short)((k0 * 8) | ((k1 * 8) << 8));
    } else {
        // ---- A/B prefix tables ----
        int v = (blockIdx.x - 128) * 256 + threadIdx.x;  // o*IN + i
        float s = scaler[v];
        float4 w0 = *(const float4*)(w + v * G_DIM);
        float4 w1 = *(const float4*)(w + v * G_DIM + 4);
        float wv[G_DIM] = {w0.x, w0.y, w0.z, w0.w, w1.x, w1.y, w1.z, w1.w};
        float Ep = __expf(s * step);
        float ep = __expf(s * g0);
        float Eq = rcp_f(Ep);
        float eq = rcp_f(ep);
        float p[G_DIM], q[G_DIM];
#pragma unroll
        for (int g = 0; g < G_DIM; g++) {
            p[g] = wv[g] * ep;  ep *= Ep;   // w_g * e^{ s*grid_g}
            q[g] = wv[g] * eq;  eq *= Eq;   // w_g * e^{-s*grid_g}
        }
        float A[9], Bv[9];
        A[0] = 0.f;
#pragma unroll
        for (int k = 0; k < 8; k++) A[k + 1] = A[k] + p[k];
        Bv[8] = 0.f;
#pragma unroll
        for (int k = 7; k >= 0; k--) Bv[k] = Bv[k + 1] + q[k];
#pragma unroll
        for (int k = 0; k < 9; k++) g_AB2[k][v] = make_float2(A[k], Bv[k]);
        g_AB2[9][v] = make_float2(s, base_[v] * LN2);
    }
}

// ---------------------------------------------------------------------------
// Main kernel: CTA = 32b x 8o x IPART i; thread = (b-pair, o); stage + consume.
//   contribution = A_k*2^{-t} + B_k*2^{t} + base'*xn',  t = s*xn'
// ---------------------------------------------------------------------------
__global__ __launch_bounds__(128, 7)
void k_main(float* __restrict__ out)
{
    __shared__ float          sh_xn[IC][XNSTR];     // 4.6KB
    __shared__ unsigned short sh_kp[BT / 2][IC];    // 1KB
    __shared__ float          sh_ab[IC * IISTR];    // 20.7KB

    const int tid     = threadIdx.x;
    const int o_local = tid & 7;         // o = o0 + o_local
    const int bpair   = tid >> 3;        // 0..15 -> b = b0 + 2*bpair (+0/1)
    const int o0      = blockIdx.x * OT;
    const int b0      = blockIdx.y * BT;
    const int i00     = blockIdx.z * IPART;

    float acc0 = 0.f, acc1 = 0.f;

#pragma unroll 1
    for (int c = 0; c < NCH; c++) {
        const int i0 = i00 + c * IC;

        // ---- stage xn: 32 ii x 32 b floats (4KB) ----
        {
            int ii = tid >> 3, b4 = (tid & 7) * 4;
#pragma unroll
            for (int j = 0; j < 2; j++) {
                float4 v = *(const float4*)&g_xn[(i0 + ii + j * 16) * B_DIM + b0 + b4];
                *(float4*)&sh_xn[ii + j * 16][b4] = v;
            }
        }
        // ---- stage k-pack: 16 pairs x 32 ii u16 (1KB) ----
        {
            int pr = tid >> 3, i4 = (tid & 7) * 4;
            *(uint2*)&sh_kp[pr][i4] =
                *(const uint2*)&g_kp[(b0 / 2 + pr) * IN_DIM + i0 + i4];
        }
        // ---- stage AB cells: 10 k x 8 o x 32 ii float2 (20KB), float4 = 2 ii ----
#pragma unroll
        for (int un = 0; un < 10; un++) {
            int e   = tid + un * 128;      // 0..1279
            int row = e >> 4;              // 0..79
            int k   = row >> 3;            // 0..9
            int o   = row & 7;
            int iip = (e & 15) * 2;        // ii pair
            float4 v = *(const float4*)&g_AB2[k][(o0 + o) * IN_DIM + i0 + iip];
            float* cell = &sh_ab[iip * IISTR + o * CELLF + 2 * k];
            *(float2*)cell           = make_float2(v.x, v.y);
            *(float2*)(cell + IISTR) = make_float2(v.z, v.w);
        }
        __syncthreads();

        // ---- consume: 2 triples per ii per thread ----
        const float* rbase = sh_ab + o_local * CELLF;
        const unsigned short* kprow = &sh_kp[bpair][0];
#pragma unroll
        for (int ii = 0; ii < IC; ii++) {
            float2 xn2 = *(const float2*)&sh_xn[ii][2 * bpair];
            unsigned int kk = kprow[ii];
            const char* rp = (const char*)(rbase + ii * IISTR);
            float2 sb = *(const float2*)(rp + 72);            // {s, base*ln2}
            float2 a0 = *(const float2*)(rp + (kk & 0xFFu));  // {A,B} for b
            float2 a1 = *(const float2*)(rp + (kk >> 8));     // {A,B} for b+1
            float t0 = sb.x * xn2.x;
            float t1 = sb.x * xn2.y;
            float u0 = ex2_f(t0), r0 = rcp_f(u0);
            float u1 = ex2_f(t1), r1 = rcp_f(u1);
            acc0 = fmaf(a0.x, r0, fmaf(a0.y, u0, fmaf(sb.y, xn2.x, acc0)));
            acc1 = fmaf(a1.x, r1, fmaf(a1.y, u1, fmaf(sb.y, xn2.y, acc1)));
        }
        __syncthreads();
    }

    // Z=4: four commutative one-shot atomic adds per output from 0
    int b = b0 + 2 * bpair, o = o0 + o_local;
    atomicAdd(&out[b * OUT_DIM + o],       acc0);
    atomicAdd(&out[(b + 1) * OUT_DIM + o], acc1);
}

// ---------------------------------------------------------------------------
extern "C" void kernel_launch(void* const* d_in, const int* in_sizes, int n_in,
                              void* d_out, int out_size)
{
    const float* x      = (const float*)d_in[0];
    const float* w      = (const float*)d_in[1];
    const float* scaler = (const float*)d_in[2];
    const float* base   = (const float*)d_in[3];
    const float* grid   = (const float*)d_in[4];
    float* out = (float*)d_out;

    cudaMemsetAsync(out, 0, (size_t)out_size * sizeof(float));
    k_prep<<<384, 256>>>(x, w, scaler, base, grid);
    dim3 g(OUT_DIM / OT, B_DIM / BT, Z);    // 32 x 8 x 4 = 1024 CTAs
    k_main<<<g, 128>>>(out);
}

// round 12
// speedup vs baseline: 1.5000x; 1.2451x over previous
#include <cuda_runtime.h>

#define B_DIM   256
#define OUT_DIM 256
#define IN_DIM  256
#define G_DIM   8
#define LOG2E   1.44269504088896340736f
#define LN2     0.69314718055994530942f

#define OT    8          // o per CTA (4 o-pairs)
#define BT    64         // b per CTA (32 b-pairs)
#define IC    16         // i-chunk
#define Z     8
#define IPART (IN_DIM / Z)      // 32
#define NCH   (IPART / IC)      // 2

// shared layout constants
#define AB_F4_PER_II 41         // 4 opairs * 10 float4 + 1 pad  (656B per ii, 16B-mult)
#define XN_STR 68               // floats per ii row (272B, 16B-mult, bank stride 4)
#define KP_STR 20               // u16 per bpair row (40B, 8B-mult, bank stride 10)

// Precomputed scratch (device globals; no allocation).
__device__ float          g_xn[IN_DIM * B_DIM];            // [i][b]: tanh(x)*log2e
__device__ unsigned short g_kp[(B_DIM / 2) * IN_DIM];      // [bpair][i]: (k0*16)|(k1*16)<<8
__device__ float4         g_ABP[10][(OUT_DIM / 2) * IN_DIM];
// g_ABP[k][op*IN+i]: k<9 -> {A_k(2op), B_k(2op), A_k(2op+1), B_k(2op+1)}
//                    k=9 -> {s(2op), b'(2op), s(2op+1), b'(2op+1)}   (b' = base*ln2)

__device__ __forceinline__ float rcp_f(float a) {
    float r; asm("rcp.approx.f32 %0, %1;" : "=f"(r) : "f"(a)); return r;
}
__device__ __forceinline__ float ex2_f(float a) {
    float r; asm("ex2.approx.f32 %0, %1;" : "=f"(r) : "f"(a)); return r;
}
__device__ __forceinline__ float tanh_fast(float x) {
    float e = __expf(2.0f * x);                 // saturates correctly at +/-inf
    return 1.0f - __fdividef(2.0f, e + 1.0f);
}

// ---------------------------------------------------------------------------
// Prep: blocks [0,128) -> xn/k; blocks [128,256) -> paired A/B tables + zero out.
// ---------------------------------------------------------------------------
__global__ __launch_bounds__(256)
void k_prep(const float* __restrict__ x,
            const float* __restrict__ w,
            const float* __restrict__ scaler,
            const float* __restrict__ base_,
            const float* __restrict__ grid,
            float* __restrict__ out)
{
    const float g0    = __ldg(grid);
    const float g7    = __ldg(grid + (G_DIM - 1));
    const float step  = (g7 - g0) * (1.0f / (float)(G_DIM - 1));
    const float inv_h = (float)(G_DIM - 1) / (g7 - g0);

    if (blockIdx.x < 128) {
        // ---- xn / k ----
        int u    = blockIdx.x * 256 + threadIdx.x;   // 0..32767
        int pair = u >> 8;                           // 0..127
        int i    = u & 255;
        int b    = pair * 2;
        float xn0 = tanh_fast(x[b * IN_DIM + i]);
        float xn1 = tanh_fast(x[(b + 1) * IN_DIM + i]);
        int k0 = 1 + __float2int_rd((xn0 - g0) * inv_h);
        int k1 = 1 + __float2int_rd((xn1 - g0) * inv_h);
        k0 = max(0, min(8, k0));
        k1 = max(0, min(8, k1));
        *(float2*)&g_xn[i * B_DIM + b] = make_float2(xn0 * LOG2E, xn1 * LOG2E);
        g_kp[pair * IN_DIM + i] = (unsigned short)((k0 * 16) | ((k1 * 16) << 8));
    } else {
        // ---- paired A/B prefix tables (2 o's per thread) + zero the output ----
        int v  = (blockIdx.x - 128) * 256 + threadIdx.x;  // op*IN + i, 0..32767
        ((float2*)out)[v] = make_float2(0.f, 0.f);        // zero out (replaces memset)

        int op = v >> 8;
        int i  = v & 255;
        float Aab[2][9], Bab[2][9], sv[2], bv[2];
#pragma unroll
        for (int h = 0; h < 2; h++) {
            int row = (2 * op + h) * IN_DIM + i;
            float s = scaler[row];
            float4 w0 = *(const float4*)(w + row * G_DIM);
            float4 w1 = *(const float4*)(w + row * G_DIM + 4);
            float wv[G_DIM] = {w0.x, w0.y, w0.z, w0.w, w1.x, w1.y, w1.z, w1.w};
            float Ep = __expf(s * step);
            float ep = __expf(s * g0);
            float Eq = rcp_f(Ep);
            float eq = rcp_f(ep);
            float p[G_DIM], q[G_DIM];
#pragma unroll
            for (int g = 0; g < G_DIM; g++) {
                p[g] = wv[g] * ep;  ep *= Ep;   // w_g * e^{ s*grid_g}
                q[g] = wv[g] * eq;  eq *= Eq;   // w_g * e^{-s*grid_g}
            }
            Aab[h][0] = 0.f;
#pragma unroll
            for (int k = 0; k < 8; k++) Aab[h][k + 1] = Aab[h][k] + p[k];
            Bab[h][8] = 0.f;
#pragma unroll
            for (int k = 7; k >= 0; k--) Bab[h][k] = Bab[h][k + 1] + q[k];
            sv[h] = s;
            bv[h] = base_[row] * LN2;
        }
#pragma unroll
        for (int k = 0; k < 9; k++)
            g_ABP[k][v] = make_float4(Aab[0][k], Bab[0][k], Aab[1][k], Bab[1][k]);
        g_ABP[9][v] = make_float4(sv[0], bv[0], sv[1], bv[1]);
    }
}

// ---------------------------------------------------------------------------
// Main: CTA = 64b x 8o x IPART i; thread = (2b x 2o); stage + consume.
//   contribution = A_k*2^{-t} + B_k*2^{t} + b'*xn',  t = s*xn'
// ---------------------------------------------------------------------------
__global__ __launch_bounds__(128, 6)
void k_main(float* __restrict__ out)
{
    __shared__ __align__(16) float          sh_ab[IC * AB_F4_PER_II * 4];  // 10.5KB
    __shared__ __align__(16) float          sh_xn[IC][XN_STR];             // 4.3KB
    __shared__ __align__(8)  unsigned short sh_kp[BT / 2][KP_STR];         // 1.3KB

    const int tid   = threadIdx.x;
    const int opair = tid & 3;           // o = o0 + 2*opair (+0/1)
    const int bpair = tid >> 2;          // 0..31 -> b = b0 + 2*bpair (+0/1)
    const int o0    = blockIdx.x * OT;
    const int opg0  = blockIdx.x * (OT / 2);     // global o-pair base
    const int b0    = blockIdx.y * BT;
    const int i00   = blockIdx.z * IPART;

    float acc00 = 0.f, acc01 = 0.f, acc10 = 0.f, acc11 = 0.f;

#pragma unroll 1
    for (int c = 0; c < NCH; c++) {
        const int i0 = i00 + c * IC;

        // ---- stage xn: 16 ii x 64 b floats (4KB), float4 granularity ----
#pragma unroll
        for (int j = 0; j < 2; j++) {
            int e  = tid + j * 128;          // 0..255
            int ii = e >> 4;
            int b4 = (e & 15) * 4;
            float4 v = *(const float4*)&g_xn[(i0 + ii) * B_DIM + b0 + b4];
            *(float4*)&sh_xn[ii][b4] = v;
        }
        // ---- stage k-pack: 32 bpairs x 16 ii u16 (1KB), uint2 granularity ----
        {
            int pr = tid >> 2;
            int i4 = (tid & 3) * 4;
            *(uint2*)&sh_kp[pr][i4] =
                *(const uint2*)&g_kp[(b0 / 2 + pr) * IN_DIM + i0 + i4];
        }
        // ---- stage AB cells: 10 k x 4 op x 16 ii float4 (10.2KB) ----
#pragma unroll
        for (int un = 0; un < 5; un++) {
            int e  = tid + un * 128;         // 0..639
            int ii = e & 15;
            int op = (e >> 4) & 3;
            int k  = e >> 6;
            float4 v = *(const float4*)&g_ABP[k][(opg0 + op) * IN_DIM + i0 + ii];
            *(((float4*)sh_ab) + ii * AB_F4_PER_II + op * 10 + k) = v;
        }
        __syncthreads();

        // ---- consume: 4 triples (2b x 2o) per ii per thread ----
        const char* rbase = (const char*)sh_ab + opair * 160;
#pragma unroll
        for (int ii = 0; ii < IC; ii++) {
            float2 xn2 = *(const float2*)&sh_xn[ii][2 * bpair];
            unsigned int kk = sh_kp[bpair][ii];
            const char* rp = rbase + ii * (AB_F4_PER_II * 16);
            float4 sbq = *(const float4*)(rp + 144);           // {s,b',s',b''}
            float4 gA  = *(const float4*)(rp + (kk & 0xFFu));  // {A,B,A',B'} @ k0 (b)
            float4 gB  = *(const float4*)(rp + (kk >> 8));     // {A,B,A',B'} @ k1 (b+1)
            float t00 = sbq.x * xn2.x;      // (o , b)
            float t01 = sbq.z * xn2.x;      // (o', b)
            float t10 = sbq.x * xn2.y;      // (o , b+1)
            float t11 = sbq.z * xn2.y;      // (o', b+1)
            float u00 = ex2_f(t00), r00 = rcp_f(u00);
            float u01 = ex2_f(t01), r01 = rcp_f(u01);
            float u10 = ex2_f(t10), r10 = rcp_f(u10);
            float u11 = ex2_f(t11), r11 = rcp_f(u11);
            acc00 = fmaf(gA.x, r00, fmaf(gA.y, u00, fmaf(sbq.y, xn2.x, acc00)));
            acc01 = fmaf(gA.z, r01, fmaf(gA.w, u01, fmaf(sbq.w, xn2.x, acc01)));
            acc10 = fmaf(gB.x, r10, fmaf(gB.y, u10, fmaf(sbq.y, xn2.y, acc10)));
            acc11 = fmaf(gB.z, r11, fmaf(gB.w, u11, fmaf(sbq.w, xn2.y, acc11)));
        }
        __syncthreads();
    }

    // Z=8: one-shot commutative atomic adds from a zeroed buffer -> deterministic
    int b = b0 + 2 * bpair;
    int o = o0 + 2 * opair;
    atomicAdd(&out[b * OUT_DIM + o],           acc00);
    atomicAdd(&out[b * OUT_DIM + o + 1],       acc01);
    atomicAdd(&out[(b + 1) * OUT_DIM + o],     acc10);
    atomicAdd(&out[(b + 1) * OUT_DIM + o + 1], acc11);
}

// ---------------------------------------------------------------------------
extern "C" void kernel_launch(void* const* d_in, const int* in_sizes, int n_in,
                              void* d_out, int out_size)
{
    const float* x      = (const float*)d_in[0];
    const float* w      = (const float*)d_in[1];
    const float* scaler = (const float*)d_in[2];
    const float* base   = (const float*)d_in[3];
    const float* grid   = (const float*)d_in[4];
    float* out = (float*)d_out;

    k_prep<<<256, 256>>>(x, w, scaler, base, grid, out);
    dim3 g(OUT_DIM / OT, B_DIM / BT, Z);    // 32 x 4 x 8 = 1024 CTAs
    k_main<<<g, 128>>>(out);
}